// round 11
// baseline (speedup 1.0000x reference)
#include <cuda_runtime.h>
#include <cuda_bf16.h>
#include <math.h>

// Problem constants
#define T_STEPS 2048
#define H_DIM   1024
#define G_DIM   4096   // 4*H
#define NCTA    128    // <= SM count -> co-resident (required for dataflow scan)

typedef unsigned long long ull;

// ---------------- device scratch (static: no allocation allowed) ------------
__device__ float g_gx[(size_t)T_STEPS * G_DIM];     // 32 MB precomputed gate inputs
// per-step tagged hidden state: packet = {low: h bits, high: tag}; tag==s valid.
__device__ ull g_hp[(size_t)(T_STEPS + 1) * H_DIM];

// packed fp32x2 FMA (Blackwell FFMA2 — only reachable via PTX)
__device__ __forceinline__ ull fma2(ull a, ull b, ull c) {
    ull d;
    asm("fma.rn.f32x2 %0, %1, %2, %3;" : "=l"(d) : "l"(a), "l"(b), "l"(c));
    return d;
}
__device__ __forceinline__ ull pack2(float x, float y) {
    ull d;
    asm("mov.b64 %0, {%1, %2};" : "=l"(d) : "f"(x), "f"(y));
    return d;
}

// fast activations (validated R5: passed with rel_err 8.55e-07)
__device__ __forceinline__ float sigmoid_fast(float x) {
    return 1.f / (1.f + __expf(-x));
}
__device__ __forceinline__ float tanh_fast(float x) {
    return 2.f / (1.f + __expf(-2.f * x)) - 1.f;
}

// ---------------- init: invalidate all tags, set h0 -------------------------
__global__ void init_kernel() {
    size_t i = (size_t)blockIdx.x * blockDim.x + threadIdx.x;
    size_t n = (size_t)(T_STEPS + 1) * H_DIM;
    if (i < n) {
        g_hp[i] = (i < H_DIM) ? 0ull : 0xFFFFFFFF00000000ull;
    }
}

// no-op kernel: shifts ncu's -s 5 -c 1 capture window onto lstm_scan
__global__ void align_kernel() {}

// ---------------- GEMM: gx[t][r] = dot(emb[tok[t]], W_ih[r]) + b ------------
// f32x2-packed inner loop (proven R6/R7).
__global__ void __launch_bounds__(256) gemm_gx(
    const int* __restrict__ tokens, const float* __restrict__ emb,
    const float* __restrict__ Wih,  const float* __restrict__ bih,
    const float* __restrict__ bhh)
{
    __shared__ float As[16][128];
    __shared__ float Bs[16][128];
    __shared__ int   tok[128];

    const int tid = threadIdx.x;
    const int n0  = blockIdx.x * 128;
    const int m0  = blockIdx.y * 128;

    if (tid < 128) tok[tid] = tokens[m0 + tid];
    __syncthreads();

    const int trow = tid >> 4;
    const int tcol = tid & 15;
    const int lm   = tid >> 2;
    const int lk   = (tid & 3) << 2;

    ull acc2[8][4];
#pragma unroll
    for (int i = 0; i < 8; ++i)
#pragma unroll
        for (int jp = 0; jp < 4; ++jp) acc2[i][jp] = 0ull;

    for (int kt = 0; kt < H_DIM; kt += 16) {
#pragma unroll
        for (int r = 0; r < 2; ++r) {
            const int m = lm + r * 64;
            float4 v = *reinterpret_cast<const float4*>(
                emb + (size_t)tok[m] * H_DIM + kt + lk);
            As[lk + 0][m] = v.x; As[lk + 1][m] = v.y;
            As[lk + 2][m] = v.z; As[lk + 3][m] = v.w;
            float4 u = *reinterpret_cast<const float4*>(
                Wih + (size_t)(n0 + m) * H_DIM + kt + lk);
            Bs[lk + 0][m] = u.x; Bs[lk + 1][m] = u.y;
            Bs[lk + 2][m] = u.z; Bs[lk + 3][m] = u.w;
        }
        __syncthreads();

#pragma unroll
        for (int kk = 0; kk < 16; ++kk) {
            float a[8];
            float4 a0 = *reinterpret_cast<const float4*>(&As[kk][trow * 8]);
            float4 a1 = *reinterpret_cast<const float4*>(&As[kk][trow * 8 + 4]);
            a[0]=a0.x; a[1]=a0.y; a[2]=a0.z; a[3]=a0.w;
            a[4]=a1.x; a[5]=a1.y; a[6]=a1.z; a[7]=a1.w;
            const ull* bp = reinterpret_cast<const ull*>(&Bs[kk][tcol * 8]);
            ull b2[4] = {bp[0], bp[1], bp[2], bp[3]};
#pragma unroll
            for (int i = 0; i < 8; ++i) {
                ull ai = pack2(a[i], a[i]);
#pragma unroll
                for (int jp = 0; jp < 4; ++jp)
                    acc2[i][jp] = fma2(ai, b2[jp], acc2[i][jp]);
            }
        }
        __syncthreads();
    }

    float2 bias[4];
#pragma unroll
    for (int jp = 0; jp < 4; ++jp) {
        const int n = n0 + tcol * 8 + jp * 2;
        bias[jp].x = bih[n]     + bhh[n];
        bias[jp].y = bih[n + 1] + bhh[n + 1];
    }
#pragma unroll
    for (int i = 0; i < 8; ++i) {
        const int m = m0 + trow * 8 + i;
        float2* orow = reinterpret_cast<float2*>(
            g_gx + (size_t)m * G_DIM + n0 + tcol * 8);
#pragma unroll
        for (int jp = 0; jp < 4; ++jp) {
            float2 f = *reinterpret_cast<float2*>(&acc2[i][jp]);
            f.x += bias[jp].x;
            f.y += bias[jp].y;
            orow[jp] = f;
        }
    }
}

// ---------------- persistent LSTM scan (scalar-poll dataflow) ----------------
// 128 CTAs x 512 threads. W_hh register-resident (64 regs/thread).
// Handshake (R4/R7/R10-proven): publish {h, tag=s+1} via st.release.gpu.u64;
// consumers spin with SCALAR ld.acquire.gpu.u64 ONLY (vector polls tear —
// R3/R6/R9). Parallel epilogue (warp 0, lane 4j+g), fast activations (R5).
__global__ void __launch_bounds__(512, 1) lstm_scan(
    const float* __restrict__ Whh, float* __restrict__ out)
{
    const int tid  = threadIdx.x;
    const int b    = blockIdx.x;
    const int gate = tid >> 7;        // 0..3
    const int t    = tid & 127;       // k-slot
    const int k0   = t << 3;          // 0..1016
    const int lane = tid & 31;
    const int wig  = (tid >> 5) & 3;  // warp within gate group

    // W_hh slice into registers as f32x2 pairs: w2[j][pair]
    ull w2[8][4];
#pragma unroll
    for (int j = 0; j < 8; ++j) {
        const ull* wr = reinterpret_cast<const ull*>(
            Whh + (size_t)(gate * H_DIM + (b << 3) + j) * H_DIM + k0);
#pragma unroll
        for (int p = 0; p < 4; ++p) w2[j][p] = wr[p];
    }

    __shared__ float hs[H_DIM];
    __shared__ float red[4][4][9];    // [gate][warp-in-gate][j], padded

    // epilogue mapping (warp 0): lane = 4*j + g
    const int ej = lane >> 2;         // row 0..7
    const int eg = lane & 3;          // gate 0..3
    const int ejg = (b << 3) + ej;    // global j
    float c = 0.f;                    // cell state lives in lanes 4j (eg==0)

#pragma unroll 1
    for (int s = 0; s < T_STEPS; ++s) {
        // warp 0 prefetches gx for its gate/row (independent of h)
        float pg = 0.f;
        if (tid < 32) {
            pg = __ldg(g_gx + (size_t)s * G_DIM + eg * H_DIM + ejg);
        }

        // merged spin: two SCALAR acquire loads issued back-to-back per iter
        {
            const ull* src = g_hp + (size_t)s * H_DIM + tid * 2;
            const unsigned expd = (unsigned)s;
            ull p0, p1;
            for (;;) {
                asm volatile("ld.acquire.gpu.global.u64 %0, [%1];"
                             : "=l"(p0) : "l"(src) : "memory");
                asm volatile("ld.acquire.gpu.global.u64 %0, [%1];"
                             : "=l"(p1) : "l"(src + 1) : "memory");
                if (((unsigned)(p0 >> 32) == expd) &
                    ((unsigned)(p1 >> 32) == expd)) break;
            }
            hs[tid * 2]     = __uint_as_float((unsigned)p0);
            hs[tid * 2 + 1] = __uint_as_float((unsigned)p1);
        }
        __syncthreads();

        // h pairs for my k range
        ull h2[4];
        {
            const ull* hp = reinterpret_cast<const ull*>(hs + k0);
#pragma unroll
            for (int p = 0; p < 4; ++p) h2[p] = hp[p];
        }

        // 8 rows x 4 packed FMAs
        ull acc2[8];
#pragma unroll
        for (int j = 0; j < 8; ++j) {
            ull a = 0;
#pragma unroll
            for (int p = 0; p < 4; ++p) a = fma2(w2[j][p], h2[p], a);
            acc2[j] = a;
        }
        float acc[8];
#pragma unroll
        for (int j = 0; j < 8; ++j) {
            float2 f = *reinterpret_cast<float2*>(&acc2[j]);
            acc[j] = f.x + f.y;
        }

        // row-folding butterfly reduction: 16 shfls total
#pragma unroll
        for (int j = 0; j < 8; ++j)
            acc[j] += __shfl_xor_sync(0xFFFFFFFFu, acc[j], 16);
        float b4[4];
#pragma unroll
        for (int j = 0; j < 4; ++j) {
            b4[j] = (lane & 16) ? acc[j + 4] : acc[j];
            b4[j] += __shfl_xor_sync(0xFFFFFFFFu, b4[j], 8);
        }
        float b2[2];
#pragma unroll
        for (int j = 0; j < 2; ++j) {
            b2[j] = (lane & 8) ? b4[j + 2] : b4[j];
            b2[j] += __shfl_xor_sync(0xFFFFFFFFu, b2[j], 4);
        }
        float b1 = (lane & 4) ? b2[1] : b2[0];
        b1 += __shfl_xor_sync(0xFFFFFFFFu, b1, 2);
        b1 += __shfl_xor_sync(0xFFFFFFFFu, b1, 1);
        if ((lane & 3) == 0) red[gate][wig][(lane >> 2) & 7] = b1;
        __syncthreads();

        // parallel epilogue: warp 0, lane 4j+g handles gate g of row j
        if (tid < 32) {
            float sum = pg + red[eg][0][ej] + red[eg][1][ej]
                           + red[eg][2][ej] + red[eg][3][ej];
            float act = (eg == 2) ? tanh_fast(sum) : sigmoid_fast(sum);
            float f_ = __shfl_down_sync(0xFFFFFFFFu, act, 1);
            float g_ = __shfl_down_sync(0xFFFFFFFFu, act, 2);
            float o_ = __shfl_down_sync(0xFFFFFFFFu, act, 3);
            if (eg == 0) {
                c = fmaf(f_, c, act * g_);
                float h = o_ * tanh_fast(c);
                ull pkt = (ull)__float_as_uint(h) | ((ull)(unsigned)(s + 1) << 32);
                ull* dst = g_hp + (size_t)(s + 1) * H_DIM + ejg;
                asm volatile("st.release.gpu.global.u64 [%0], %1;"
                             :: "l"(dst), "l"(pkt) : "memory");
                if (s == T_STEPS - 1) { out[ejg] = h; out[H_DIM + ejg] = c; }
            }
        }
        // no end-of-step barrier: per-step buffers + tags gate the next read
    }
}

// ---------------- launcher ---------------------------------------------------
extern "C" void kernel_launch(void* const* d_in, const int* in_sizes, int n_in,
                              void* d_out, int out_size) {
    const int*   tokens = (const int*)d_in[0];
    const float* emb    = (const float*)d_in[1];
    const float* Wih    = (const float*)d_in[2];
    const float* Whh    = (const float*)d_in[3];
    const float* bih    = (const float*)d_in[4];
    const float* bhh    = (const float*)d_in[5];
    float* out = (float*)d_out;

    // 3 no-op launches: shift ncu's "-s 5 -c 1" window onto lstm_scan (launch #5)
    align_kernel<<<1, 32>>>();
    align_kernel<<<1, 32>>>();
    align_kernel<<<1, 32>>>();

    init_kernel<<<(int)(((size_t)(T_STEPS + 1) * H_DIM + 1023) / 1024), 1024>>>();

    dim3 ggrid(G_DIM / 128, T_STEPS / 128);  // 32 x 16
    gemm_gx<<<ggrid, 256>>>(tokens, emb, Wih, bih, bhh);

    lstm_scan<<<NCTA, 512>>>(Whh, out);
}

// round 12
// speedup vs baseline: 1.4438x; 1.4438x over previous
#include <cuda_runtime.h>
#include <cuda_bf16.h>
#include <math.h>

// Problem constants
#define T_STEPS 2048
#define H_DIM   1024
#define G_DIM   4096   // 4*H
#define NCTA    128    // <= SM count -> co-resident (required for dataflow scan)
#define NPKT    512    // h packets per step (2 h values per 8B packet)
#define SENT32  0x7FC00000u   // NaN bits: never produced by finite LSTM math

typedef unsigned long long ull;

// ---------------- device scratch (static: no allocation allowed) ------------
__device__ float g_gx[(size_t)T_STEPS * G_DIM];       // 32 MB gate inputs
// per-step pair-packed h: packet p of step s = {h[2p], h[2p+1]} bits.
// Sentinel NaN in both halves means "not yet written".
__device__ ull g_hpk[(size_t)(T_STEPS + 1) * NPKT];

// packed fp32x2 FMA (Blackwell FFMA2 — only reachable via PTX)
__device__ __forceinline__ ull fma2(ull a, ull b, ull c) {
    ull d;
    asm("fma.rn.f32x2 %0, %1, %2, %3;" : "=l"(d) : "l"(a), "l"(b), "l"(c));
    return d;
}
__device__ __forceinline__ ull pack2(float x, float y) {
    ull d;
    asm("mov.b64 %0, {%1, %2};" : "=l"(d) : "f"(x), "f"(y));
    return d;
}

// fast activations (validated R5/R11)
__device__ __forceinline__ float sigmoid_fast(float x) {
    return 1.f / (1.f + __expf(-x));
}
__device__ __forceinline__ float tanh_fast(float x) {
    return 2.f / (1.f + __expf(-2.f * x)) - 1.f;
}

// ---------------- init: sentinel everywhere, h0 = 0 --------------------------
__global__ void init_kernel() {
    size_t i = (size_t)blockIdx.x * blockDim.x + threadIdx.x;
    size_t n = (size_t)(T_STEPS + 1) * NPKT;
    if (i < n) {
        g_hpk[i] = (i < NPKT) ? 0ull
                              : (((ull)SENT32 << 32) | (ull)SENT32);
    }
}

// ---------------- GEMM: gx[t][r] = dot(emb[tok[t]], W_ih[r]) + b ------------
// f32x2-packed inner loop (proven R6+).
__global__ void __launch_bounds__(256) gemm_gx(
    const int* __restrict__ tokens, const float* __restrict__ emb,
    const float* __restrict__ Wih,  const float* __restrict__ bih,
    const float* __restrict__ bhh)
{
    __shared__ float As[16][128];
    __shared__ float Bs[16][128];
    __shared__ int   tok[128];

    const int tid = threadIdx.x;
    const int n0  = blockIdx.x * 128;
    const int m0  = blockIdx.y * 128;

    if (tid < 128) tok[tid] = tokens[m0 + tid];
    __syncthreads();

    const int trow = tid >> 4;
    const int tcol = tid & 15;
    const int lm   = tid >> 2;
    const int lk   = (tid & 3) << 2;

    ull acc2[8][4];
#pragma unroll
    for (int i = 0; i < 8; ++i)
#pragma unroll
        for (int jp = 0; jp < 4; ++jp) acc2[i][jp] = 0ull;

    for (int kt = 0; kt < H_DIM; kt += 16) {
#pragma unroll
        for (int r = 0; r < 2; ++r) {
            const int m = lm + r * 64;
            float4 v = *reinterpret_cast<const float4*>(
                emb + (size_t)tok[m] * H_DIM + kt + lk);
            As[lk + 0][m] = v.x; As[lk + 1][m] = v.y;
            As[lk + 2][m] = v.z; As[lk + 3][m] = v.w;
            float4 u = *reinterpret_cast<const float4*>(
                Wih + (size_t)(n0 + m) * H_DIM + kt + lk);
            Bs[lk + 0][m] = u.x; Bs[lk + 1][m] = u.y;
            Bs[lk + 2][m] = u.z; Bs[lk + 3][m] = u.w;
        }
        __syncthreads();

#pragma unroll
        for (int kk = 0; kk < 16; ++kk) {
            float a[8];
            float4 a0 = *reinterpret_cast<const float4*>(&As[kk][trow * 8]);
            float4 a1 = *reinterpret_cast<const float4*>(&As[kk][trow * 8 + 4]);
            a[0]=a0.x; a[1]=a0.y; a[2]=a0.z; a[3]=a0.w;
            a[4]=a1.x; a[5]=a1.y; a[6]=a1.z; a[7]=a1.w;
            const ull* bp = reinterpret_cast<const ull*>(&Bs[kk][tcol * 8]);
            ull b2[4] = {bp[0], bp[1], bp[2], bp[3]};
#pragma unroll
            for (int i = 0; i < 8; ++i) {
                ull ai = pack2(a[i], a[i]);
#pragma unroll
                for (int jp = 0; jp < 4; ++jp)
                    acc2[i][jp] = fma2(ai, b2[jp], acc2[i][jp]);
            }
        }
        __syncthreads();
    }

    float2 bias[4];
#pragma unroll
    for (int jp = 0; jp < 4; ++jp) {
        const int n = n0 + tcol * 8 + jp * 2;
        bias[jp].x = bih[n]     + bhh[n];
        bias[jp].y = bih[n + 1] + bhh[n + 1];
    }
#pragma unroll
    for (int i = 0; i < 8; ++i) {
        const int m = m0 + trow * 8 + i;
        float2* orow = reinterpret_cast<float2*>(
            g_gx + (size_t)m * G_DIM + n0 + tcol * 8);
#pragma unroll
        for (int jp = 0; jp < 4; ++jp) {
            float2 f = *reinterpret_cast<float2*>(&acc2[i][jp]);
            f.x += bias[jp].x;
            f.y += bias[jp].y;
            orow[jp] = f;
        }
    }
}

// ---------------- persistent LSTM scan (pair-packed sentinel dataflow) -------
// 128 CTAs x 512 threads. W_hh register-resident (64 regs/thread).
// Publish: lanes 0,8,16,24 of warp 0 store {h[2j],h[2j+1]} via st.cg.u64
// (8B scalar = proven non-tearing width; values self-contained -> no fences).
// Consume: each thread spins on ONE scalar ld.cg.u64 against NaN sentinels.
__global__ void __launch_bounds__(512, 1) lstm_scan(
    const float* __restrict__ Whh, float* __restrict__ out)
{
    const int tid  = threadIdx.x;
    const int b    = blockIdx.x;
    const int gate = tid >> 7;        // 0..3
    const int t    = tid & 127;       // k-slot
    const int k0   = t << 3;          // 0..1016
    const int lane = tid & 31;
    const int wig  = (tid >> 5) & 3;  // warp within gate group

    // W_hh slice into registers as f32x2 pairs: w2[j][pair]
    ull w2[8][4];
#pragma unroll
    for (int j = 0; j < 8; ++j) {
        const ull* wr = reinterpret_cast<const ull*>(
            Whh + (size_t)(gate * H_DIM + (b << 3) + j) * H_DIM + k0);
#pragma unroll
        for (int p = 0; p < 4; ++p) w2[j][p] = wr[p];
    }

    __shared__ float hs[H_DIM];
    __shared__ float red[4][4][9];    // [gate][warp-in-gate][j], padded

    // epilogue mapping (warp 0): lane = 4*j + g
    const int ej = lane >> 2;         // row 0..7
    const int eg = lane & 3;          // gate 0..3
    const int ejg = (b << 3) + ej;    // global j
    float c = 0.f;                    // cell state lives in lanes 4j (eg==0)

#pragma unroll 1
    for (int s = 0; s < T_STEPS; ++s) {
        // warp 0 prefetches gx for its gate/row (independent of h)
        float pg = 0.f;
        if (tid < 32) {
            pg = __ldg(g_gx + (size_t)s * G_DIM + eg * H_DIM + ejg);
        }

        // single scalar spin: one packet (= 2 h values) per thread
        {
            const ull* src = g_hpk + (size_t)s * NPKT + tid;
            ull p;
            for (;;) {
                asm volatile("ld.global.cg.u64 %0, [%1];"
                             : "=l"(p) : "l"(src));
                if (((unsigned)p != SENT32) &
                    ((unsigned)(p >> 32) != SENT32)) break;
                __nanosleep(24);
            }
            hs[tid * 2]     = __uint_as_float((unsigned)p);
            hs[tid * 2 + 1] = __uint_as_float((unsigned)(p >> 32));
        }
        __syncthreads();

        // h pairs for my k range
        ull h2[4];
        {
            const ull* hp = reinterpret_cast<const ull*>(hs + k0);
#pragma unroll
            for (int p = 0; p < 4; ++p) h2[p] = hp[p];
        }

        // 8 rows x 4 packed FMAs
        ull acc2[8];
#pragma unroll
        for (int j = 0; j < 8; ++j) {
            ull a = 0;
#pragma unroll
            for (int p = 0; p < 4; ++p) a = fma2(w2[j][p], h2[p], a);
            acc2[j] = a;
        }
        float acc[8];
#pragma unroll
        for (int j = 0; j < 8; ++j) {
            float2 f = *reinterpret_cast<float2*>(&acc2[j]);
            acc[j] = f.x + f.y;
        }

        // row-folding butterfly reduction: 16 shfls total
#pragma unroll
        for (int j = 0; j < 8; ++j)
            acc[j] += __shfl_xor_sync(0xFFFFFFFFu, acc[j], 16);
        float b4[4];
#pragma unroll
        for (int j = 0; j < 4; ++j) {
            b4[j] = (lane & 16) ? acc[j + 4] : acc[j];
            b4[j] += __shfl_xor_sync(0xFFFFFFFFu, b4[j], 8);
        }
        float b2[2];
#pragma unroll
        for (int j = 0; j < 2; ++j) {
            b2[j] = (lane & 8) ? b4[j + 2] : b4[j];
            b2[j] += __shfl_xor_sync(0xFFFFFFFFu, b2[j], 4);
        }
        float b1 = (lane & 4) ? b2[1] : b2[0];
        b1 += __shfl_xor_sync(0xFFFFFFFFu, b1, 2);
        b1 += __shfl_xor_sync(0xFFFFFFFFu, b1, 1);
        if ((lane & 3) == 0) red[gate][wig][(lane >> 2) & 7] = b1;
        __syncthreads();

        // parallel epilogue: warp 0, lane 4j+g handles gate g of row j
        if (tid < 32) {
            float sum = pg + red[eg][0][ej] + red[eg][1][ej]
                           + red[eg][2][ej] + red[eg][3][ej];
            float act = (eg == 2) ? tanh_fast(sum) : sigmoid_fast(sum);
            float f_ = __shfl_down_sync(0xFFFFFFFFu, act, 1);
            float g_ = __shfl_down_sync(0xFFFFFFFFu, act, 2);
            float o_ = __shfl_down_sync(0xFFFFFFFFu, act, 3);
            float h = 0.f;
            if (eg == 0) {
                c = fmaf(f_, c, act * g_);
                h = o_ * tanh_fast(c);
                if (s == T_STEPS - 1) { out[ejg] = h; out[H_DIM + ejg] = c; }
            }
            // pair-pack: lane 4j (j even) grabs h[j+1] from lane 4j+4
            float hodd = __shfl_down_sync(0xFFFFFFFFu, h, 4);
            if ((eg == 0) && ((ej & 1) == 0)) {
                ull pkt = pack2(h, hodd);
                ull* dst = g_hpk + (size_t)(s + 1) * NPKT + (b << 2) + (ej >> 1);
                asm volatile("st.global.cg.u64 [%0], %1;" :: "l"(dst), "l"(pkt));
            }
        }
        // no end-of-step barrier: per-step buffers + sentinels gate reads
    }
}

// ---------------- launcher ---------------------------------------------------
extern "C" void kernel_launch(void* const* d_in, const int* in_sizes, int n_in,
                              void* d_out, int out_size) {
    const int*   tokens = (const int*)d_in[0];
    const float* emb    = (const float*)d_in[1];
    const float* Wih    = (const float*)d_in[2];
    const float* Whh    = (const float*)d_in[3];
    const float* bih    = (const float*)d_in[4];
    const float* bhh    = (const float*)d_in[5];
    float* out = (float*)d_out;

    init_kernel<<<(int)(((size_t)(T_STEPS + 1) * NPKT + 1023) / 1024), 1024>>>();

    dim3 ggrid(G_DIM / 128, T_STEPS / 128);  // 32 x 16
    gemm_gx<<<ggrid, 256>>>(tokens, emb, Wih, bih, bhh);

    lstm_scan<<<NCTA, 512>>>(Whh, out);
}